// round 5
// baseline (speedup 1.0000x reference)
#include <cuda_runtime.h>

#define NB   128
#define NBP  135          // stride ≡ 7 (mod 32): cell->bank map is a perfect permutation
#define NBLK 296          // 2 CTAs/SM
#define NTHR 768
#define NWARP (NTHR / 32)

__device__ float g_hist[NB * NB];   // zeroed at load; re-zeroed by normalize each replay
__device__ float g_sum;
__device__ float g_scale;

// Elliptical stencil di^2+dj^2 <= 10 (37 cells), split so each ATOMS is conflict-free:
// set1 (32 cells): keys (7*(di+3)+(dj+3)) mod 32 cover banks 0..31 exactly once.
__constant__ signed char C1I[32] = {-3,-3,-3, -2,-2,-2,-2,-2, -1,-1,-1,-1,-1,-1,-1,
                                     0,0,0,0,0,0,0, 1,1,1,1,1,1, 2,2,2, 3};
__constant__ signed char C1J[32] = {-1,0,1, -2,-1,0,1,2, -3,-2,-1,0,1,2,3,
                                    -3,-2,-1,0,1,2,3, -3,-2,-1,0,1,2, -1,0,1, 0};
// set2 (5 cells, lanes 0..4): banks {2,4,8,12,14} — also conflict-free.
__constant__ signed char C2I[5] = {1, 2, 2, 3, 3};
__constant__ signed char C2J[5] = {3,-2, 2,-1, 1};

__global__ void __launch_bounds__(NTHR, 2)
accum_kernel(const float* __restrict__ x,
             const float* __restrict__ ex,
             const float* __restrict__ ey,
             int n) {
    extern __shared__ float sh[];   // NB * NBP floats
    __shared__ float blk_sum;
    for (int i = threadIdx.x; i < NB * NBP; i += NTHR) sh[i] = 0.0f;
    if (threadIdx.x == 0) blk_sum = 0.0f;
    __syncthreads();

    const float bwx = ex[1] - ex[0];
    const float bwy = ey[1] - ey[0];
    const float inv_bwx = 1.0f / bwx;
    const float inv_bwy = 1.0f / bwy;
    const float c0x = 0.5f * (ex[0] + ex[1]);
    const float c0y = 0.5f * (ey[0] + ey[1]);

    const int lane = threadIdx.x & 31;
    const int gw   = blockIdx.x * NWARP + (threadIdx.x >> 5);
    const int nw   = NBLK * NWARP;

    // per-lane stencil constants (loaded once)
    const int   i1 = C1I[lane],  j1 = C1J[lane];
    const float f1i = (float)i1, f1j = (float)j1;
    const int   off1 = i1 * NBP + j1;
    const int   l2 = (lane < 5) ? lane : 0;
    const int   i2 = C2I[l2],  j2 = C2J[l2];
    const float f2i = (float)i2, f2j = (float)j2;
    const int   off2 = i2 * NBP + j2;
    const bool  has2 = (lane < 5);

    for (int p0 = gw * 32; p0 < n; p0 += nw * 32) {
        int pi = p0 + lane;
        float ux, uy;
        if (pi < n) {
            // x is [n,6]; dims 0,1 adjacent, 24B row stride keeps 8B alignment
            float2 pt = __ldg((const float2*)(x + pi * 6));
            ux = (pt.x - c0x) * inv_bwx;    // position in bin-center units
            uy = (pt.y - c0y) * inv_bwy;
        } else {
            ux = 1.0e9f; uy = 1.0e9f;       // forces all bounds checks false
        }
        #pragma unroll 4
        for (int k = 0; k < 32; ++k) {
            float uxk = __shfl_sync(0xffffffffu, ux, k);
            float uyk = __shfl_sync(0xffffffffu, uy, k);
            int ix0 = __float2int_rn(uxk);
            int iy0 = __float2int_rn(uyk);
            float fx = uxk - (float)ix0;    // in [-0.5, 0.5]
            float fy = uyk - (float)iy0;
            int baseaddr = ix0 * NBP + iy0;
            // cell 1 (all 32 lanes, banks 0..31 — conflict-free)
            float dx = fx - f1i, dy = fy - f1j;
            float w = __expf(-0.5f * (dx * dx + dy * dy));
            unsigned ib = (unsigned)(ix0 + i1), jb = (unsigned)(iy0 + j1);
            if (ib < NB && jb < NB) atomicAdd(&sh[baseaddr + off1], w);
            // cell 2 (lanes 0..4, distinct banks)
            float dx2 = fx - f2i, dy2 = fy - f2j;
            float w2 = __expf(-0.5f * (dx2 * dx2 + dy2 * dy2));
            unsigned ib2 = (unsigned)(ix0 + i2), jb2 = (unsigned)(iy0 + j2);
            if (has2 && ib2 < NB && jb2 < NB) atomicAdd(&sh[baseaddr + off2], w2);
        }
    }

    __syncthreads();
    // flush block-private hist to global; accumulate block total for normalization
    float my_sum = 0.0f;
    for (int i = threadIdx.x; i < NB * NB; i += NTHR) {
        float v = sh[(i >> 7) * NBP + (i & (NB - 1))];
        my_sum += v;
        if (v != 0.0f) atomicAdd(&g_hist[i], v);
    }
    #pragma unroll
    for (int off = 16; off > 0; off >>= 1)
        my_sum += __shfl_down_sync(0xffffffffu, my_sum, off);
    if ((threadIdx.x & 31) == 0) atomicAdd(&blk_sum, my_sum);
    __syncthreads();
    if (threadIdx.x == 0) atomicAdd(&g_sum, blk_sum);
}

__global__ void scale_kernel(const float* __restrict__ ex,
                             const float* __restrict__ ey) {
    float bwx = ex[1] - ex[0];
    float bwy = ey[1] - ey[0];
    g_scale = 1.0f / (g_sum * bwx * bwy);
    g_sum = 0.0f;   // reset for next graph replay
}

__global__ void normalize_kernel(float* __restrict__ out) {
    int i = blockIdx.x * blockDim.x + threadIdx.x;   // 64 CTAs x 256 = NB*NB
    out[i] = g_hist[i] * g_scale;
    g_hist[i] = 0.0f;   // reset for next graph replay
}

extern "C" void kernel_launch(void* const* d_in, const int* in_sizes, int n_in,
                              void* d_out, int out_size) {
    const float* x  = (const float*)d_in[0];
    const float* ex = (const float*)d_in[1];
    const float* ey = (const float*)d_in[2];
    int n = in_sizes[0] / 6;

    const int SMEM = NB * NBP * (int)sizeof(float);   // 69120 B
    cudaFuncSetAttribute(accum_kernel, cudaFuncAttributeMaxDynamicSharedMemorySize, SMEM);

    accum_kernel<<<NBLK, NTHR, SMEM>>>(x, ex, ey, n);
    scale_kernel<<<1, 1>>>(ex, ey);
    normalize_kernel<<<(NB * NB) / 256, 256>>>((float*)d_out);
}

// round 6
// speedup vs baseline: 1.1285x; 1.1285x over previous
#include <cuda_runtime.h>

#define NB      128
#define APR     6                    // apron: stencil radius 3 + worst-case off-grid center 3
#define ROWS    (NB + 2*APR)         // 140
#define STRIDE  167                  // >= 140, and 167 % 32 == 7 -> bank permutation holds
#define NBLK    296                  // 2 CTAs/SM
#define NTHR    768
#define NWARP   (NTHR / 32)
#define NEG_HALF_LOG2E (-0.7213475204444817f)

__device__ float g_hist[NB * NB];   // zeroed at load; re-zeroed by normalize each replay
__device__ float g_sum;
__device__ float g_scale;

// Elliptical stencil di^2+dj^2 <= 10 (37 cells), split so each ATOMS is conflict-free:
// set1 (32 cells): keys (7*di+dj) mod 32 cover banks 0..31 exactly once.
__constant__ signed char C1I[32] = {-3,-3,-3, -2,-2,-2,-2,-2, -1,-1,-1,-1,-1,-1,-1,
                                     0,0,0,0,0,0,0, 1,1,1,1,1,1, 2,2,2, 3};
__constant__ signed char C1J[32] = {-1,0,1, -2,-1,0,1,2, -3,-2,-1,0,1,2,3,
                                    -3,-2,-1,0,1,2,3, -3,-2,-1,0,1,2, -1,0,1, 0};
// set2 (5 cells, lanes 0..4): distinct banks.
__constant__ signed char C2I[5] = {1, 2, 2, 3, 3};
__constant__ signed char C2J[5] = {3,-2, 2,-1, 1};

__global__ void __launch_bounds__(NTHR, 2)
accum_kernel(const float* __restrict__ x,
             const float* __restrict__ ex,
             const float* __restrict__ ey,
             int n) {
    extern __shared__ float sh[];   // ROWS * STRIDE floats (incl. apron)
    __shared__ float blk_sum;
    for (int i = threadIdx.x; i < ROWS * STRIDE; i += NTHR) sh[i] = 0.0f;
    if (threadIdx.x == 0) blk_sum = 0.0f;
    __syncthreads();

    const float bwx = ex[1] - ex[0];
    const float bwy = ey[1] - ey[0];
    const float inv_bwx = 1.0f / bwx;
    const float inv_bwy = 1.0f / bwy;
    const float c0x = 0.5f * (ex[0] + ex[1]);
    const float c0y = 0.5f * (ey[0] + ey[1]);

    const int lane = threadIdx.x & 31;
    const int gw   = blockIdx.x * NWARP + (threadIdx.x >> 5);
    const int nw   = NBLK * NWARP;

    // per-lane stencil constants
    const float f1i = (float)C1I[lane], f1j = (float)C1J[lane];
    const int   off1 = C1I[lane] * STRIDE + C1J[lane];
    const int   l2 = (lane < 5) ? lane : 0;
    const float f2i = (float)C2I[l2], f2j = (float)C2J[l2];
    const int   off2 = C2I[l2] * STRIDE + C2J[l2];
    const bool  has2 = (lane < 5);

    for (int p0 = gw * 32; p0 < n; p0 += nw * 32) {
        int pi = p0 + lane;
        // ---- per-lane precompute for own point ----
        int   base = 0;
        float fx = 0.0f, fy = 0.0f;
        bool  valid = (pi < n);
        if (valid) {
            float2 pt = __ldg((const float2*)(x + pi * 6));   // dims 0,1; 24B row stride
            float ux = (pt.x - c0x) * inv_bwx;   // bin-center units
            float uy = (pt.y - c0y) * inv_bwy;
            float rx = rintf(ux), ry = rintf(uy);
            int ix0 = (int)rx, iy0 = (int)ry;
            fx = ux - rx;                        // in [-0.5, 0.5]
            fy = uy - ry;
            // points with ix0/iy0 outside [-3,130] touch no in-range bin
            valid = ((unsigned)(ix0 + 3) <= 133u) && ((unsigned)(iy0 + 3) <= 133u);
            base = (ix0 + APR) * STRIDE + (iy0 + APR);
        }
        unsigned vm = __ballot_sync(0xffffffffu, valid);

        #pragma unroll 4
        for (int k = 0; k < 32; ++k) {
            if (!((vm >> k) & 1u)) continue;     // warp-uniform predicate, rarely taken
            int   bk  = __shfl_sync(0xffffffffu, base, k);
            float fxk = __shfl_sync(0xffffffffu, fx, k);
            float fyk = __shfl_sync(0xffffffffu, fy, k);
            // cell 1: all 32 lanes, banks are a permutation -> conflict-free ATOMS
            float dx = fxk - f1i, dy = fyk - f1j;
            float t  = fmaf(dy, dy, dx * dx);
            float w  = exp2f(t * NEG_HALF_LOG2E);
            atomicAdd(&sh[bk + off1], w);
            // cell 2: lanes 0..4, distinct banks
            float dx2 = fxk - f2i, dy2 = fyk - f2j;
            float t2  = fmaf(dy2, dy2, dx2 * dx2);
            float w2  = exp2f(t2 * NEG_HALF_LOG2E);
            if (has2) atomicAdd(&sh[bk + off2], w2);
        }
    }

    __syncthreads();
    // flush interior of block-private hist to global; accumulate block total
    float my_sum = 0.0f;
    for (int i = threadIdx.x; i < NB * NB; i += NTHR) {
        int r = i >> 7, c = i & (NB - 1);
        float v = sh[(r + APR) * STRIDE + (c + APR)];
        my_sum += v;
        if (v != 0.0f) atomicAdd(&g_hist[i], v);
    }
    #pragma unroll
    for (int off = 16; off > 0; off >>= 1)
        my_sum += __shfl_down_sync(0xffffffffu, my_sum, off);
    if ((threadIdx.x & 31) == 0) atomicAdd(&blk_sum, my_sum);
    __syncthreads();
    if (threadIdx.x == 0) atomicAdd(&g_sum, blk_sum);
}

__global__ void scale_kernel(const float* __restrict__ ex,
                             const float* __restrict__ ey) {
    float bwx = ex[1] - ex[0];
    float bwy = ey[1] - ey[0];
    g_scale = 1.0f / (g_sum * bwx * bwy);
    g_sum = 0.0f;   // reset for next graph replay
}

__global__ void normalize_kernel(float* __restrict__ out) {
    int i = blockIdx.x * blockDim.x + threadIdx.x;   // 64 CTAs x 256 = NB*NB
    out[i] = g_hist[i] * g_scale;
    g_hist[i] = 0.0f;   // reset for next graph replay
}

extern "C" void kernel_launch(void* const* d_in, const int* in_sizes, int n_in,
                              void* d_out, int out_size) {
    const float* x  = (const float*)d_in[0];
    const float* ex = (const float*)d_in[1];
    const float* ey = (const float*)d_in[2];
    int n = in_sizes[0] / 6;

    const int SMEM = ROWS * STRIDE * (int)sizeof(float);   // 93520 B
    cudaFuncSetAttribute(accum_kernel, cudaFuncAttributeMaxDynamicSharedMemorySize, SMEM);

    accum_kernel<<<NBLK, NTHR, SMEM>>>(x, ex, ey, n);
    scale_kernel<<<1, 1>>>(ex, ey);
    normalize_kernel<<<(NB * NB) / 256, 256>>>((float*)d_out);
}